// round 15
// baseline (speedup 1.0000x reference)
#include <cuda_runtime.h>
#include <cuda_bf16.h>
#include <cstdint>

#define NN 100000
#define EE 1600000
#define DH 128
#define NTILES ((NN + 127) / 128)   // 782
#define GRID_P 148
#define NB_SCAN ((NN + 511) / 512)  // 196
#define HIST_BLOCKS (EE / 256)      // 6250

// ---------------- device scratch ----------------
__device__ __align__(16) uint16_t g_xH[NN * DH];   // h planes (GEMM x-input / head input)
__device__ __align__(16) uint16_t g_xL[NN * DH];
__device__ float g_h[NN * DH];                     // fp32 h (layer-1 gather source)
__device__ int   g_cnt[NN];          // zero-init at load; re-zeroed by k_head_tc tail
__device__ int   g_cur[NN];
__device__ int   g_off[NN];
__device__ int   g_srcsorted[EE];
__device__ unsigned long long g_pkt[NB_SCAN];
__device__ __align__(16) uint16_t g_WB0[2 * 4 * 128 * 72];
__device__ __align__(16) uint16_t g_WB1[2 * 4 * 128 * 72];
__device__ __align__(16) uint16_t g_WBh[2 * 2 * 64 * 72];

// ---------------- helpers ----------------
__device__ __forceinline__ void split2(float a, float b, uint32_t& h, uint32_t& l) {
    __nv_bfloat16 ha = __float2bfloat16_rn(a);
    __nv_bfloat16 hb = __float2bfloat16_rn(b);
    __nv_bfloat16 la = __float2bfloat16_rn(a - __bfloat162float(ha));
    __nv_bfloat16 lb = __float2bfloat16_rn(b - __bfloat162float(hb));
    h = (uint32_t)__bfloat16_as_ushort(ha) | ((uint32_t)__bfloat16_as_ushort(hb) << 16);
    l = (uint32_t)__bfloat16_as_ushort(la) | ((uint32_t)__bfloat16_as_ushort(lb) << 16);
}
__device__ __forceinline__ float mish2(float v) {
    float t = __expf(fminf(v, 30.f));
    float r = t * t + 2.f * t;
    return v * (r / (r + 2.f));
}
__device__ __forceinline__ void mma_bf16(float* c, const uint32_t* a, const uint32_t* b) {
    asm volatile(
        "mma.sync.aligned.m16n8k16.row.col.f32.bf16.bf16.f32 "
        "{%0,%1,%2,%3}, {%4,%5,%6,%7}, {%8,%9}, {%0,%1,%2,%3};"
        : "+f"(c[0]), "+f"(c[1]), "+f"(c[2]), "+f"(c[3])
        : "r"(a[0]), "r"(a[1]), "r"(a[2]), "r"(a[3]), "r"(b[0]), "r"(b[1]));
}
__device__ __forceinline__ void ldsm4(uint32_t* r, uint32_t a) {
    asm volatile("ldmatrix.sync.aligned.m8n8.x4.shared.b16 {%0,%1,%2,%3}, [%4];"
        : "=r"(r[0]), "=r"(r[1]), "=r"(r[2]), "=r"(r[3]) : "r"(a));
}

// ---------------- fused hist + weight prep ----------------
__device__ __forceinline__ void prep_layer_elem(const float* Wl, const float* Wr,
                                                uint16_t* outw, int idx) {
    int n = idx >> 6;
    int kg = (idx & 63) * 4;
    const float* Ws = (kg < 128) ? Wl : Wr;
    float4 v = *(const float4*)&Ws[n * 128 + (kg & 127)];
    uint32_t h01, h23, l01, l23;
    split2(v.x, v.y, h01, l01);
    split2(v.z, v.w, h23, l23);
    int c = kg >> 6, kk = kg & 63;
    *(uint2*)&outw[((0 * 4 + c) * 128 + n) * 72 + kk] = make_uint2(h01, h23);
    *(uint2*)&outw[((4 + c) * 128 + n) * 72 + kk]     = make_uint2(l01, l23);
}
__global__ void k_hist_prep(const int* __restrict__ edge,
                            const float* __restrict__ Wl0, const float* __restrict__ Wr0,
                            const float* __restrict__ Wl1, const float* __restrict__ Wr1,
                            const float* __restrict__ Wh) {
    int b = blockIdx.x;
    int t = threadIdx.x;
    if (b < HIST_BLOCKS) {
        int e = b * 256 + t;
        atomicAdd(&g_cnt[edge[EE + e]], 1);
    } else {
        int pb = b - HIST_BLOCKS;    // 0..71
        if (pb < 32) {
            prep_layer_elem(Wl0, Wr0, g_WB0, pb * 256 + t);
        } else if (pb < 64) {
            prep_layer_elem(Wl1, Wr1, g_WB1, (pb - 32) * 256 + t);
        } else {
            int idx = (pb - 64) * 256 + t;
            int n = idx >> 5;
            int kg = (idx & 31) * 4;
            float4 v = *(const float4*)&Wh[n * 128 + kg];
            uint32_t h01, h23, l01, l23;
            split2(v.x, v.y, h01, l01);
            split2(v.z, v.w, h23, l23);
            int c = kg >> 6, kk = kg & 63;
            *(uint2*)&g_WBh[((0 * 2 + c) * 64 + n) * 72 + kk] = make_uint2(h01, h23);
            *(uint2*)&g_WBh[((2 + c) * 64 + n) * 72 + kk]     = make_uint2(l01, l23);
        }
    }
}
// single-pass decoupled-lookback exclusive scan of g_cnt -> g_off
__global__ void k_scan() {
    __shared__ int s[512];
    __shared__ int s_prefix;
    int t = threadIdx.x, b = blockIdx.x;
    int i = b * 512 + t;
    int v = (i < NN) ? g_cnt[i] : 0;
    s[t] = v;
    __syncthreads();
    #pragma unroll
    for (int off = 1; off < 512; off <<= 1) {
        int add = (t >= off) ? s[t - off] : 0;
        __syncthreads();
        s[t] += add;
        __syncthreads();
    }
    int total = s[511];
    if (t == 0) {
        atomicExch(&g_pkt[b], (1ull << 62) | (unsigned long long)total);
        long long prefix = 0;
        for (int j = b - 1; j >= 0; j--) {
            unsigned long long p;
            do { p = atomicAdd(&g_pkt[j], 0ull); } while ((p >> 62) == 0ull);
            prefix += (long long)(p & 0x3FFFFFFFFFFFFFFFull);
            if ((p >> 62) == 2ull) break;
        }
        atomicExch(&g_pkt[b], (2ull << 62) | (unsigned long long)(prefix + total));
        s_prefix = (int)prefix;
    }
    __syncthreads();
    if (i < NN) g_off[i] = s[t] - v + s_prefix;
}
__global__ void k_scatter(const int* __restrict__ edge) {
    int e = blockIdx.x * blockDim.x + threadIdx.x;
    if (e < EE) {
        int src = edge[e];
        int dst = edge[EE + e];
        int pos = g_off[dst] + atomicAdd(&g_cur[dst], 1);
        g_srcsorted[pos] = src;
    }
}

// ---------------- staging primitives ----------------
template <int NIT> struct StageRegsT { uint4 rH[NIT], rL[NIT]; };

template <int NIT>
__device__ __forceinline__ void stage_load_planes(StageRegsT<NIT>& s, const uint16_t* pH,
                                                  const uint16_t* pL, int row0, int cb,
                                                  int t, int stride) {
    #pragma unroll
    for (int i = 0; i < NIT; i++) {
        int v = t + i * stride, row = v >> 3, f = v & 7, gr = row0 + row;
        if (gr < NN) {
            s.rH[i] = *(const uint4*)(pH + gr * 128 + cb + f * 8);
            s.rL[i] = *(const uint4*)(pL + gr * 128 + cb + f * 8);
        } else {
            s.rH[i] = make_uint4(0, 0, 0, 0);
            s.rL[i] = make_uint4(0, 0, 0, 0);
        }
    }
}
template <int NIT>
__device__ __forceinline__ void stage_load_f32(StageRegsT<NIT>& s, const float* xf,
                                               int row0, int cb16, int t, int stride) {
    const float4* x4 = (const float4*)xf;
    #pragma unroll
    for (int i = 0; i < NIT; i++) {
        int v = t + i * stride, row = v >> 3, f = v & 7, gr = row0 + row;
        float4 a = make_float4(0.f, 0.f, 0.f, 0.f);
        float4 b = make_float4(0.f, 0.f, 0.f, 0.f);
        if (gr < NN) {
            a = x4[gr * 32 + cb16 + f * 2];
            b = x4[gr * 32 + cb16 + f * 2 + 1];
        }
        uint32_t h01, h23, h45, h67, l01, l23, l45, l67;
        split2(a.x, a.y, h01, l01);
        split2(a.z, a.w, h23, l23);
        split2(b.x, b.y, h45, l45);
        split2(b.z, b.w, h67, l67);
        s.rH[i] = make_uint4(h01, h23, h45, h67);
        s.rL[i] = make_uint4(l01, l23, l45, l67);
    }
}
template <int NIT>
__device__ __forceinline__ void stage_store(const StageRegsT<NIT>& s, char* AH, char* AL,
                                            int t, int stride) {
    #pragma unroll
    for (int i = 0; i < NIT; i++) {
        int v = t + i * stride, row = v >> 3, f = v & 7;
        *(uint4*)(AH + row * 144 + f * 16) = s.rH[i];
        *(uint4*)(AL + row * 144 + f * 16) = s.rL[i];
    }
}

// ================= fused persistent layer: per-tile aggregation + GEMM =================
// out = mish( [mean_agg | x] @ [Wl|Wr]^T + b )
// Per tile: 16 warps gather/reduce the tile's 128 rows (8 rows/warp) from feat fp32,
// normalize, split to bf16 hi/lo, write straight into smem A-slots (chunks 0,1).
// Then MMA c0 (stage x-c2), c1 (stage x-c3), c2, c3; fused epilogue.
// smem: bias 512 | A slots 2x36864 (hi+lo each) | W 147456 => 221696 B
#define L_SM_A    512
#define L_SM_W    (512 + 4 * 18432)
#define L_SMEM_BYTES (L_SM_W + 147456)

__global__ __launch_bounds__(512, 1) void k_layer_fused(
    const float* __restrict__ feat,              // gather source fp32 (x or g_h)
    const uint16_t* xH, const uint16_t* xL,      // x planes (layer 1; may alias out)
    const float* __restrict__ xf32,              // x fp32 (layer 0) if non-null
    const uint16_t* __restrict__ wprep, const float* __restrict__ bias,
    float* __restrict__ hout, uint16_t* outH, uint16_t* outL, int write_f32) {
    extern __shared__ __align__(16) char smem[];
    int t = threadIdx.x;
    int wid = t >> 5, lane = t & 31;
    int g = lane >> 2, q = lane & 3;
    int wm = wid & 3, wn = wid >> 2;    // rows wm*32.., cols wn*32..

    {
        const uint4* src = (const uint4*)wprep;
        uint4* dst = (uint4*)(smem + L_SM_W);
        #pragma unroll
        for (int it = 0; it < 18; it++) dst[t + it * 512] = src[t + it * 512];
    }
    if (t < 128) ((float*)smem)[t] = bias[t];

    uint32_t smemS = (uint32_t)__cvta_generic_to_shared(smem);
    int tile4 = lane >> 3, r8 = lane & 7;
    uint32_t laneA = (uint32_t)((((tile4 & 1) * 8 + r8) * 144) + (tile4 >> 1) * 16);
    uint32_t laneB = (uint32_t)((((tile4 >> 1) * 8 + r8) * 144) + (tile4 & 1) * 16);
    uint32_t aRow0 = (uint32_t)((wm * 32) * 144);
    uint32_t bRow0 = (uint32_t)((wn * 32) * 144);

    // agg write destinations: lanes 0-15 -> slot0 (cols 0..63), 16-31 -> slot1
    char* aggHi = smem + L_SM_A + (lane >> 4) * 36864;
    char* aggLo = aggHi + 18432;
    int li = lane & 15;

    float acc[2][4][4];

    for (int tile = blockIdx.x; tile < NTILES; tile += GRID_P) {
        int row0 = tile * 128;

        // ---------- aggregation phase: 8 rows per warp ----------
        {
            const float4* f4 = (const float4*)feat;
            #pragma unroll 1
            for (int rr = 0; rr < 8; rr++) {
                int row = wid * 8 + rr;
                int gr = row0 + row;
                int start = 0, c = 0;
                if (gr < NN) { start = g_off[gr]; c = g_cnt[gr]; }
                float4 a0 = make_float4(0.f, 0.f, 0.f, 0.f);
                float4 a1 = make_float4(0.f, 0.f, 0.f, 0.f);
                for (int base = 0; base < c; base += 32) {
                    int idx = (base + lane < c) ? g_srcsorted[start + base + lane] : 0;
                    int m = min(32, c - base);
                    int j = 0;
                    for (; j + 4 <= m; j += 4) {
                        int s0 = __shfl_sync(0xffffffffu, idx, j + 0);
                        int s1 = __shfl_sync(0xffffffffu, idx, j + 1);
                        int s2 = __shfl_sync(0xffffffffu, idx, j + 2);
                        int s3 = __shfl_sync(0xffffffffu, idx, j + 3);
                        float4 v0 = __ldg(&f4[s0 * 32 + lane]);
                        float4 v1 = __ldg(&f4[s1 * 32 + lane]);
                        float4 v2 = __ldg(&f4[s2 * 32 + lane]);
                        float4 v3 = __ldg(&f4[s3 * 32 + lane]);
                        a0.x += v0.x; a0.y += v0.y; a0.z += v0.z; a0.w += v0.w;
                        a1.x += v1.x; a1.y += v1.y; a1.z += v1.z; a1.w += v1.w;
                        a0.x += v2.x; a0.y += v2.y; a0.z += v2.z; a0.w += v2.w;
                        a1.x += v3.x; a1.y += v3.y; a1.z += v3.z; a1.w += v3.w;
                    }
                    for (; j < m; j++) {
                        int s = __shfl_sync(0xffffffffu, idx, j);
                        float4 v = __ldg(&f4[s * 32 + lane]);
                        a0.x += v.x; a0.y += v.y; a0.z += v.z; a0.w += v.w;
                    }
                }
                float inv = 1.f / fmaxf((float)c, 1.f);
                float4 a = make_float4((a0.x + a1.x) * inv, (a0.y + a1.y) * inv,
                                       (a0.z + a1.z) * inv, (a0.w + a1.w) * inv);
                uint32_t h01, h23, l01, l23;
                split2(a.x, a.y, h01, l01);
                split2(a.z, a.w, h23, l23);
                *(uint2*)(aggHi + row * 144 + li * 8) = make_uint2(h01, h23);
                *(uint2*)(aggLo + row * 144 + li * 8) = make_uint2(l01, l23);
            }
        }
        __syncthreads();

        // ---------- GEMM phase ----------
        #pragma unroll
        for (int mi = 0; mi < 2; mi++)
            #pragma unroll
            for (int ni = 0; ni < 4; ni++)
                #pragma unroll
                for (int r = 0; r < 4; r++) acc[mi][ni][r] = 0.f;

        auto do_mma = [&](int c) {
            uint32_t AhS = smemS + L_SM_A + (c & 1) * 36864 + aRow0 + laneA;
            uint32_t AlS = AhS + 18432;
            uint32_t BhS = smemS + L_SM_W + c * 18432 + bRow0 + laneB;
            uint32_t BlS = BhS + 4 * 18432;
            #pragma unroll
            for (int ks = 0; ks < 4; ks++) {
                uint32_t ksb = ks * 32;
                uint32_t ah[2][4], al[2][4];
                ldsm4(ah[0], AhS + ksb);
                ldsm4(ah[1], AhS + 16 * 144 + ksb);
                ldsm4(al[0], AlS + ksb);
                ldsm4(al[1], AlS + 16 * 144 + ksb);
                #pragma unroll
                for (int nj = 0; nj < 2; nj++) {
                    uint32_t bh[4], bl[4];
                    ldsm4(bh, BhS + nj * (16 * 144) + ksb);
                    ldsm4(bl, BlS + nj * (16 * 144) + ksb);
                    #pragma unroll
                    for (int mi = 0; mi < 2; mi++) {
                        mma_bf16(acc[mi][2 * nj],     ah[mi], bh);
                        mma_bf16(acc[mi][2 * nj],     al[mi], bh);
                        mma_bf16(acc[mi][2 * nj],     ah[mi], bl);
                        mma_bf16(acc[mi][2 * nj + 1], ah[mi], bh + 2);
                        mma_bf16(acc[mi][2 * nj + 1], al[mi], bh + 2);
                        mma_bf16(acc[mi][2 * nj + 1], ah[mi], bl + 2);
                    }
                }
            }
        };

        StageRegsT<2> sr;
        // chunk2 prefetch + MMA chunk0 (slot0)
        if (xf32) stage_load_f32<2>(sr, xf32, row0, 0, t, 512);
        else      stage_load_planes<2>(sr, xH, xL, row0, 0, t, 512);
        do_mma(0);
        __syncthreads();
        {
            char* AHn = smem + L_SM_A;               // slot0 <- chunk2
            stage_store<2>(sr, AHn, AHn + 18432, t, 512);
        }
        __syncthreads();
        // chunk3 prefetch + MMA chunk1 (slot1)
        if (xf32) stage_load_f32<2>(sr, xf32, row0, 16, t, 512);
        else      stage_load_planes<2>(sr, xH, xL, row0, 64, t, 512);
        do_mma(1);
        __syncthreads();
        {
            char* AHn = smem + L_SM_A + 36864;       // slot1 <- chunk3
            stage_store<2>(sr, AHn, AHn + 18432, t, 512);
        }
        __syncthreads();
        do_mma(2);
        do_mma(3);

        // ---------- epilogue ----------
        const float* bsm = (const float*)smem;
        #pragma unroll
        for (int mi = 0; mi < 2; mi++) {
            #pragma unroll
            for (int ni = 0; ni < 4; ni++) {
                int col = wn * 32 + ni * 8 + 2 * q;
                float b0 = bsm[col], b1 = bsm[col + 1];
                int rlo = row0 + wm * 32 + mi * 16 + g;
                int rhi = rlo + 8;
                if (rlo < NN) {
                    float o0 = mish2(acc[mi][ni][0] + b0);
                    float o1 = mish2(acc[mi][ni][1] + b1);
                    if (write_f32) *(float2*)&hout[rlo * 128 + col] = make_float2(o0, o1);
                    uint32_t hh, ll;
                    split2(o0, o1, hh, ll);
                    *(uint32_t*)&outH[rlo * 128 + col] = hh;
                    *(uint32_t*)&outL[rlo * 128 + col] = ll;
                }
                if (rhi < NN) {
                    float o0 = mish2(acc[mi][ni][2] + b0);
                    float o1 = mish2(acc[mi][ni][3] + b1);
                    if (write_f32) *(float2*)&hout[rhi * 128 + col] = make_float2(o0, o1);
                    uint32_t hh, ll;
                    split2(o0, o1, hh, ll);
                    *(uint32_t*)&outH[rhi * 128 + col] = hh;
                    *(uint32_t*)&outL[rhi * 128 + col] = ll;
                }
            }
        }
        __syncthreads();   // slots fully consumed before next tile's agg overwrites
    }
}

// ================= persistent pipelined head (256 threads): out = h @ Wh^T + b =========
#define H_SM_A    512
#define H_SM_W    (512 + 4 * 18432)
#define H_SMEM_BYTES (H_SM_W + 36864)

__global__ __launch_bounds__(256, 1) void k_head_tc(
    const uint16_t* __restrict__ xH, const uint16_t* __restrict__ xL,
    const uint16_t* __restrict__ wprep, const float* __restrict__ bias,
    float* __restrict__ outp) {
    extern __shared__ __align__(16) char smem[];
    int t = threadIdx.x;
    int wid = t >> 5, lane = t & 31;
    int g = lane >> 2, q = lane & 3;

    {
        const uint4* src = (const uint4*)wprep;
        uint4* dst = (uint4*)(smem + H_SM_W);
        #pragma unroll
        for (int it = 0; it < 9; it++) dst[t + it * 256] = src[t + it * 256];
    }
    if (t < 64) ((float*)smem)[t] = bias[t];

    uint32_t smemS = (uint32_t)__cvta_generic_to_shared(smem);
    int tile4 = lane >> 3, r8 = lane & 7;
    uint32_t laneA = (uint32_t)((((tile4 & 1) * 8 + r8) * 144) + (tile4 >> 1) * 16);
    uint32_t laneB = (uint32_t)((((tile4 >> 1) * 8 + r8) * 144) + (tile4 & 1) * 16);
    uint32_t aRow0 = (uint32_t)((wid * 16) * 144);

    StageRegsT<4> sr;
    stage_load_planes<4>(sr, xH, xL, blockIdx.x * 128, 0, t, 256);
    stage_store<4>(sr, smem + H_SM_A, smem + H_SM_A + 18432, t, 256);
    __syncthreads();

    for (int tile = blockIdx.x; tile < NTILES; tile += GRID_P) {
        int row0 = tile * 128;

        float acc[8][4];
        #pragma unroll
        for (int ni = 0; ni < 8; ni++)
            #pragma unroll
            for (int r = 0; r < 4; r++) acc[ni][r] = 0.f;

        #pragma unroll
        for (int c = 0; c < 2; c++) {
            if (c < 1) stage_load_planes<4>(sr, xH, xL, row0, 64, t, 256);
            else       stage_load_planes<4>(sr, xH, xL, row0 + GRID_P * 128, 0, t, 256);

            uint32_t AhS = smemS + H_SM_A + (c & 1) * 36864 + aRow0 + laneA;
            uint32_t AlS = AhS + 18432;
            uint32_t BhS = smemS + H_SM_W + c * 9216 + laneB;
            uint32_t BlS = BhS + 2 * 9216;

            #pragma unroll
            for (int ks = 0; ks < 4; ks++) {
                uint32_t ksb = ks * 32;
                uint32_t ah[4], al[4];
                ldsm4(ah, AhS + ksb);
                ldsm4(al, AlS + ksb);
                #pragma unroll
                for (int nip = 0; nip < 4; nip++) {
                    uint32_t bh[4], bl[4];
                    ldsm4(bh, BhS + nip * (16 * 144) + ksb);
                    ldsm4(bl, BlS + nip * (16 * 144) + ksb);
                    mma_bf16(acc[2 * nip],     ah, bh);
                    mma_bf16(acc[2 * nip],     al, bh);
                    mma_bf16(acc[2 * nip],     ah, bl);
                    mma_bf16(acc[2 * nip + 1], ah, bh + 2);
                    mma_bf16(acc[2 * nip + 1], al, bh + 2);
                    mma_bf16(acc[2 * nip + 1], ah, bl + 2);
                }
            }

            {
                char* AHn = smem + H_SM_A + ((c + 1) & 1) * 36864;
                stage_store<4>(sr, AHn, AHn + 18432, t, 256);
                __syncthreads();
            }
        }

        const float* bsm = (const float*)smem;
        #pragma unroll
        for (int ni = 0; ni < 8; ni++) {
            int col = ni * 8 + 2 * q;
            float b0 = bsm[col], b1 = bsm[col + 1];
            int rlo = row0 + wid * 16 + g;
            int rhi = rlo + 8;
            if (rlo < NN)
                *(float2*)&outp[rlo * 64 + col] =
                    make_float2(acc[ni][0] + b0, acc[ni][1] + b1);
            if (rhi < NN)
                *(float2*)&outp[rhi * 64 + col] =
                    make_float2(acc[ni][2] + b0, acc[ni][3] + b1);
        }
    }

    // tail: re-zero counters for the next graph replay (this kernel is last)
    int gtid = blockIdx.x * 256 + t;
    for (int i = gtid; i < NN; i += GRID_P * 256) { g_cnt[i] = 0; g_cur[i] = 0; }
    if (gtid < NB_SCAN) g_pkt[gtid] = 0ull;
}

// ---------------- launch ----------------
extern "C" void kernel_launch(void* const* d_in, const int* in_sizes, int n_in,
                              void* d_out, int out_size) {
    (void)in_sizes; (void)n_in; (void)out_size;
    const float* x      = (const float*)d_in[0];
    const int*   edge   = (const int*)d_in[1];     // int32 on device (JAX x64 off)
    const float* W_l0   = (const float*)d_in[2];
    const float* b_l0   = (const float*)d_in[3];
    const float* W_r0   = (const float*)d_in[4];
    const float* W_l1   = (const float*)d_in[5];
    const float* b_l1   = (const float*)d_in[6];
    const float* W_r1   = (const float*)d_in[7];
    const float* W_head = (const float*)d_in[8];
    const float* b_head = (const float*)d_in[9];
    float* out = (float*)d_out;

    cudaFuncSetAttribute(k_layer_fused, cudaFuncAttributeMaxDynamicSharedMemorySize,
                         L_SMEM_BYTES);
    cudaFuncSetAttribute(k_head_tc, cudaFuncAttributeMaxDynamicSharedMemorySize,
                         H_SMEM_BYTES);

    float *h_p;
    uint16_t *xH_p, *xL_p, *wb0_p, *wb1_p, *wbh_p;
    cudaGetSymbolAddress((void**)&h_p,   g_h);
    cudaGetSymbolAddress((void**)&xH_p,  g_xH);
    cudaGetSymbolAddress((void**)&xL_p,  g_xL);
    cudaGetSymbolAddress((void**)&wb0_p, g_WB0);
    cudaGetSymbolAddress((void**)&wb1_p, g_WB1);
    cudaGetSymbolAddress((void**)&wbh_p, g_WBh);

    // counters zero at load; re-zeroed by k_head_tc tail each call.
    // launch index 3 (the ncu-profiled slot) is the fused layer-0 kernel.
    k_hist_prep<<<HIST_BLOCKS + 72, 256>>>(edge, W_l0, W_r0, W_l1, W_r1, W_head); // 0
    k_scan<<<NB_SCAN, 512>>>();                                                   // 1
    k_scatter<<<EE / 256, 256>>>(edge);                                           // 2
    // layer 0: gather x, x-chunks from fp32 x; writes h fp32 + planes
    k_layer_fused<<<GRID_P, 512, L_SMEM_BYTES>>>(x, nullptr, nullptr, x,
                                                 wb0_p, b_l0, h_p, xH_p, xL_p, 1); // 3 <- profiled
    // layer 1: gather h fp32, x-chunks from h planes; writes h1 planes only
    k_layer_fused<<<GRID_P, 512, L_SMEM_BYTES>>>(h_p, xH_p, xL_p, nullptr,
                                                 wb1_p, b_l1, h_p, xH_p, xL_p, 0); // 4
    k_head_tc<<<GRID_P, 256, H_SMEM_BYTES>>>(xH_p, xL_p, wbh_p, b_head, out);      // 5
}

// round 16
// speedup vs baseline: 1.2131x; 1.2131x over previous
#include <cuda_runtime.h>
#include <cuda_bf16.h>
#include <cstdint>

#define NN 100000
#define EE 1600000
#define DH 128
#define NTILES ((NN + 127) / 128)   // 782
#define GRID_P 148
#define NB_SCAN ((NN + 511) / 512)  // 196
#define HIST_BLOCKS (EE / 256)      // 6250

// ---------------- device scratch ----------------
__device__ __align__(16) uint16_t g_aggH[NN * DH];
__device__ __align__(16) uint16_t g_aggL[NN * DH];
__device__ __align__(16) uint16_t g_xH[NN * DH];
__device__ __align__(16) uint16_t g_xL[NN * DH];
__device__ float g_h[NN * DH];
__device__ int   g_cnt[NN];          // zero-init at load; re-zeroed by k_head_tc tail
__device__ int   g_cur[NN];
__device__ int   g_off[NN];
__device__ int   g_srcsorted[EE];
__device__ unsigned long long g_pkt[NB_SCAN];
__device__ __align__(16) uint16_t g_WB0[2 * 4 * 128 * 72];
__device__ __align__(16) uint16_t g_WB1[2 * 4 * 128 * 72];
__device__ __align__(16) uint16_t g_WBh[2 * 2 * 64 * 72];

// ---------------- helpers ----------------
__device__ __forceinline__ void split2(float a, float b, uint32_t& h, uint32_t& l) {
    __nv_bfloat16 ha = __float2bfloat16_rn(a);
    __nv_bfloat16 hb = __float2bfloat16_rn(b);
    __nv_bfloat16 la = __float2bfloat16_rn(a - __bfloat162float(ha));
    __nv_bfloat16 lb = __float2bfloat16_rn(b - __bfloat162float(hb));
    h = (uint32_t)__bfloat16_as_ushort(ha) | ((uint32_t)__bfloat16_as_ushort(hb) << 16);
    l = (uint32_t)__bfloat16_as_ushort(la) | ((uint32_t)__bfloat16_as_ushort(lb) << 16);
}
__device__ __forceinline__ float mish2(float v) {
    float t = __expf(fminf(v, 30.f));
    float r = t * t + 2.f * t;
    return v * (r / (r + 2.f));
}
__device__ __forceinline__ void mma_bf16(float* c, const uint32_t* a, const uint32_t* b) {
    asm volatile(
        "mma.sync.aligned.m16n8k16.row.col.f32.bf16.bf16.f32 "
        "{%0,%1,%2,%3}, {%4,%5,%6,%7}, {%8,%9}, {%0,%1,%2,%3};"
        : "+f"(c[0]), "+f"(c[1]), "+f"(c[2]), "+f"(c[3])
        : "r"(a[0]), "r"(a[1]), "r"(a[2]), "r"(a[3]), "r"(b[0]), "r"(b[1]));
}
__device__ __forceinline__ void ldsm4(uint32_t* r, uint32_t a) {
    asm volatile("ldmatrix.sync.aligned.m8n8.x4.shared.b16 {%0,%1,%2,%3}, [%4];"
        : "=r"(r[0]), "=r"(r[1]), "=r"(r[2]), "=r"(r[3]) : "r"(a));
}

// ---------------- fused hist + weight prep ----------------
__device__ __forceinline__ void prep_layer_elem(const float* Wl, const float* Wr,
                                                uint16_t* outw, int idx) {
    int n = idx >> 6;
    int kg = (idx & 63) * 4;
    const float* Ws = (kg < 128) ? Wl : Wr;
    float4 v = *(const float4*)&Ws[n * 128 + (kg & 127)];
    uint32_t h01, h23, l01, l23;
    split2(v.x, v.y, h01, l01);
    split2(v.z, v.w, h23, l23);
    int c = kg >> 6, kk = kg & 63;
    *(uint2*)&outw[((0 * 4 + c) * 128 + n) * 72 + kk] = make_uint2(h01, h23);
    *(uint2*)&outw[((4 + c) * 128 + n) * 72 + kk]     = make_uint2(l01, l23);
}
__global__ void k_hist_prep(const int* __restrict__ edge,
                            const float* __restrict__ Wl0, const float* __restrict__ Wr0,
                            const float* __restrict__ Wl1, const float* __restrict__ Wr1,
                            const float* __restrict__ Wh) {
    int b = blockIdx.x;
    int t = threadIdx.x;
    if (b < HIST_BLOCKS) {
        int e = b * 256 + t;
        atomicAdd(&g_cnt[edge[EE + e]], 1);
    } else {
        int pb = b - HIST_BLOCKS;    // 0..71
        if (pb < 32) {
            prep_layer_elem(Wl0, Wr0, g_WB0, pb * 256 + t);
        } else if (pb < 64) {
            prep_layer_elem(Wl1, Wr1, g_WB1, (pb - 32) * 256 + t);
        } else {
            int idx = (pb - 64) * 256 + t;
            int n = idx >> 5;
            int kg = (idx & 31) * 4;
            float4 v = *(const float4*)&Wh[n * 128 + kg];
            uint32_t h01, h23, l01, l23;
            split2(v.x, v.y, h01, l01);
            split2(v.z, v.w, h23, l23);
            int c = kg >> 6, kk = kg & 63;
            *(uint2*)&g_WBh[((0 * 2 + c) * 64 + n) * 72 + kk] = make_uint2(h01, h23);
            *(uint2*)&g_WBh[((2 + c) * 64 + n) * 72 + kk]     = make_uint2(l01, l23);
        }
    }
}
// single-pass decoupled-lookback exclusive scan of g_cnt -> g_off
__global__ void k_scan() {
    __shared__ int s[512];
    __shared__ int s_prefix;
    int t = threadIdx.x, b = blockIdx.x;
    int i = b * 512 + t;
    int v = (i < NN) ? g_cnt[i] : 0;
    s[t] = v;
    __syncthreads();
    #pragma unroll
    for (int off = 1; off < 512; off <<= 1) {
        int add = (t >= off) ? s[t - off] : 0;
        __syncthreads();
        s[t] += add;
        __syncthreads();
    }
    int total = s[511];
    if (t == 0) {
        atomicExch(&g_pkt[b], (1ull << 62) | (unsigned long long)total);
        long long prefix = 0;
        for (int j = b - 1; j >= 0; j--) {
            unsigned long long p;
            do { p = atomicAdd(&g_pkt[j], 0ull); } while ((p >> 62) == 0ull);
            prefix += (long long)(p & 0x3FFFFFFFFFFFFFFFull);
            if ((p >> 62) == 2ull) break;
        }
        atomicExch(&g_pkt[b], (2ull << 62) | (unsigned long long)(prefix + total));
        s_prefix = (int)prefix;
    }
    __syncthreads();
    if (i < NN) g_off[i] = s[t] - v + s_prefix;
}
__global__ void k_scatter(const int* __restrict__ edge) {
    int e = blockIdx.x * blockDim.x + threadIdx.x;
    if (e < EE) {
        int src = edge[e];
        int dst = edge[EE + e];
        int pos = g_off[dst] + atomicAdd(&g_cur[dst], 1);
        g_srcsorted[pos] = src;
    }
}

// ---------------- aggregation: TWO warps per node, half row (float2) each ----------
// Doubles per-node outstanding loads at LOWER register cost than one-warp-per-node.
__global__ __launch_bounds__(256) void k_aggregate(const float* __restrict__ feat,
                                                   uint16_t* __restrict__ outH,
                                                   uint16_t* __restrict__ outL) {
    int gw = (blockIdx.x * blockDim.x + threadIdx.x) >> 5;   // global warp id
    int w = gw >> 1;              // node
    int half = gw & 1;            // which half of the feature row
    if (w >= NN) return;
    int lane = threadIdx.x & 31;
    int start = g_off[w];
    int c = g_cnt[w];
    const float2* f2 = (const float2*)feat;   // row stride = 64 float2
    int colbase = half * 32 + lane;
    float2 a0 = make_float2(0.f, 0.f);
    float2 a1 = make_float2(0.f, 0.f);
    for (int base = 0; base < c; base += 32) {
        int idx = (base + lane < c) ? g_srcsorted[start + base + lane] : 0;
        int m = min(32, c - base);
        int j = 0;
        for (; j + 4 <= m; j += 4) {
            int s0 = __shfl_sync(0xffffffffu, idx, j + 0);
            int s1 = __shfl_sync(0xffffffffu, idx, j + 1);
            int s2 = __shfl_sync(0xffffffffu, idx, j + 2);
            int s3 = __shfl_sync(0xffffffffu, idx, j + 3);
            float2 v0 = __ldg(&f2[s0 * 64 + colbase]);
            float2 v1 = __ldg(&f2[s1 * 64 + colbase]);
            float2 v2 = __ldg(&f2[s2 * 64 + colbase]);
            float2 v3 = __ldg(&f2[s3 * 64 + colbase]);
            a0.x += v0.x; a0.y += v0.y;
            a1.x += v1.x; a1.y += v1.y;
            a0.x += v2.x; a0.y += v2.y;
            a1.x += v3.x; a1.y += v3.y;
        }
        for (; j < m; j++) {
            int s = __shfl_sync(0xffffffffu, idx, j);
            float2 v = __ldg(&f2[s * 64 + colbase]);
            a0.x += v.x; a0.y += v.y;
        }
    }
    float inv = 1.f / fmaxf((float)c, 1.f);
    float ax = (a0.x + a1.x) * inv;
    float ay = (a0.y + a1.y) * inv;
    uint32_t hh, ll;
    split2(ax, ay, hh, ll);
    *(uint32_t*)&outH[w * 128 + colbase * 2] = hh;
    *(uint32_t*)&outL[w * 128 + colbase * 2] = ll;
}

// ---------------- staging primitives (templated on per-thread iter count) ----------------
template <int NIT> struct StageRegsT { uint4 rH[NIT], rL[NIT]; };

template <int NIT>
__device__ __forceinline__ void stage_load_planes(StageRegsT<NIT>& s, const uint16_t* pH,
                                                  const uint16_t* pL, int row0, int cb,
                                                  int t, int stride) {
    #pragma unroll
    for (int i = 0; i < NIT; i++) {
        int v = t + i * stride, row = v >> 3, f = v & 7, gr = row0 + row;
        if (gr < NN) {
            s.rH[i] = *(const uint4*)(pH + gr * 128 + cb + f * 8);
            s.rL[i] = *(const uint4*)(pL + gr * 128 + cb + f * 8);
        } else {
            s.rH[i] = make_uint4(0, 0, 0, 0);
            s.rL[i] = make_uint4(0, 0, 0, 0);
        }
    }
}
template <int NIT>
__device__ __forceinline__ void stage_load_f32(StageRegsT<NIT>& s, const float* xf,
                                               int row0, int cb16, int t, int stride) {
    const float4* x4 = (const float4*)xf;
    #pragma unroll
    for (int i = 0; i < NIT; i++) {
        int v = t + i * stride, row = v >> 3, f = v & 7, gr = row0 + row;
        float4 a = make_float4(0.f, 0.f, 0.f, 0.f);
        float4 b = make_float4(0.f, 0.f, 0.f, 0.f);
        if (gr < NN) {
            a = x4[gr * 32 + cb16 + f * 2];
            b = x4[gr * 32 + cb16 + f * 2 + 1];
        }
        uint32_t h01, h23, h45, h67, l01, l23, l45, l67;
        split2(a.x, a.y, h01, l01);
        split2(a.z, a.w, h23, l23);
        split2(b.x, b.y, h45, l45);
        split2(b.z, b.w, h67, l67);
        s.rH[i] = make_uint4(h01, h23, h45, h67);
        s.rL[i] = make_uint4(l01, l23, l45, l67);
    }
}
template <int NIT>
__device__ __forceinline__ void stage_store(const StageRegsT<NIT>& s, char* AH, char* AL,
                                            int t, int stride) {
    #pragma unroll
    for (int i = 0; i < NIT; i++) {
        int v = t + i * stride, row = v >> 3, f = v & 7;
        *(uint4*)(AH + row * 144 + f * 16) = s.rH[i];
        *(uint4*)(AL + row * 144 + f * 16) = s.rL[i];
    }
}

// ================= persistent pipelined layer GEMM: 512 threads, 16 warps =========
// warp tile 32x32; smem: bias 512 | A dbuf 2x36864 | W 147456 => 221696 B
#define L_SM_A    512
#define L_SM_W    (512 + 4 * 18432)
#define L_SMEM_BYTES (L_SM_W + 147456)

__global__ __launch_bounds__(512, 1) void k_layer_tc(
    const uint16_t* __restrict__ aggH, const uint16_t* __restrict__ aggL,
    const uint16_t* xH, const uint16_t* xL,
    const float* __restrict__ xf32,
    const uint16_t* __restrict__ wprep, const float* __restrict__ bias,
    float* __restrict__ hout, uint16_t* outH, uint16_t* outL, int write_f32) {
    extern __shared__ __align__(16) char smem[];
    int t = threadIdx.x;
    int wid = t >> 5, lane = t & 31;
    int g = lane >> 2, q = lane & 3;
    int wm = wid & 3, wn = wid >> 2;    // rows wm*32.., cols wn*32..

    {
        const uint4* src = (const uint4*)wprep;
        uint4* dst = (uint4*)(smem + L_SM_W);
        #pragma unroll
        for (int it = 0; it < 18; it++) dst[t + it * 512] = src[t + it * 512];
    }
    if (t < 128) ((float*)smem)[t] = bias[t];

    uint32_t smemS = (uint32_t)__cvta_generic_to_shared(smem);
    int tile4 = lane >> 3, r8 = lane & 7;
    uint32_t laneA = (uint32_t)((((tile4 & 1) * 8 + r8) * 144) + (tile4 >> 1) * 16);
    uint32_t laneB = (uint32_t)((((tile4 >> 1) * 8 + r8) * 144) + (tile4 & 1) * 16);
    uint32_t aRow0 = (uint32_t)((wm * 32) * 144);
    uint32_t bRow0 = (uint32_t)((wn * 32) * 144);

    auto load_chunk = [&](StageRegsT<2>& s, int cc, int r0) {
        if (cc < 2)
            stage_load_planes<2>(s, aggH, aggL, r0, cc * 64, t, 512);
        else if (xf32)
            stage_load_f32<2>(s, xf32, r0, (cc - 2) * 16, t, 512);
        else
            stage_load_planes<2>(s, xH, xL, r0, (cc - 2) * 64, t, 512);
    };

    StageRegsT<2> sr;
    load_chunk(sr, 0, blockIdx.x * 128);
    stage_store<2>(sr, smem + L_SM_A, smem + L_SM_A + 18432, t, 512);
    __syncthreads();

    for (int tile = blockIdx.x; tile < NTILES; tile += GRID_P) {
        int row0 = tile * 128;

        float acc[2][4][4];
        #pragma unroll
        for (int mi = 0; mi < 2; mi++)
            #pragma unroll
            for (int ni = 0; ni < 4; ni++)
                #pragma unroll
                for (int r = 0; r < 4; r++) acc[mi][ni][r] = 0.f;

        #pragma unroll
        for (int c = 0; c < 4; c++) {
            if (c < 3) load_chunk(sr, c + 1, row0);
            else       load_chunk(sr, 0, row0 + GRID_P * 128);

            uint32_t AhS = smemS + L_SM_A + (c & 1) * 36864 + aRow0 + laneA;
            uint32_t AlS = AhS + 18432;
            uint32_t BhS = smemS + L_SM_W + c * 18432 + bRow0 + laneB;
            uint32_t BlS = BhS + 4 * 18432;

            #pragma unroll
            for (int ks = 0; ks < 4; ks++) {
                uint32_t ksb = ks * 32;
                uint32_t ah[2][4], al[2][4];
                ldsm4(ah[0], AhS + ksb);
                ldsm4(ah[1], AhS + 16 * 144 + ksb);
                ldsm4(al[0], AlS + ksb);
                ldsm4(al[1], AlS + 16 * 144 + ksb);
                #pragma unroll
                for (int nj = 0; nj < 2; nj++) {
                    uint32_t bh[4], bl[4];
                    ldsm4(bh, BhS + nj * (16 * 144) + ksb);
                    ldsm4(bl, BlS + nj * (16 * 144) + ksb);
                    #pragma unroll
                    for (int mi = 0; mi < 2; mi++) {
                        mma_bf16(acc[mi][2 * nj],     ah[mi], bh);
                        mma_bf16(acc[mi][2 * nj],     al[mi], bh);
                        mma_bf16(acc[mi][2 * nj],     ah[mi], bl);
                        mma_bf16(acc[mi][2 * nj + 1], ah[mi], bh + 2);
                        mma_bf16(acc[mi][2 * nj + 1], al[mi], bh + 2);
                        mma_bf16(acc[mi][2 * nj + 1], ah[mi], bl + 2);
                    }
                }
            }

            {
                char* AHn = smem + L_SM_A + ((c + 1) & 1) * 36864;
                stage_store<2>(sr, AHn, AHn + 18432, t, 512);
                __syncthreads();
            }
        }

        const float* bsm = (const float*)smem;
        #pragma unroll
        for (int mi = 0; mi < 2; mi++) {
            #pragma unroll
            for (int ni = 0; ni < 4; ni++) {
                int col = wn * 32 + ni * 8 + 2 * q;
                float b0 = bsm[col], b1 = bsm[col + 1];
                int rlo = row0 + wm * 32 + mi * 16 + g;
                int rhi = rlo + 8;
                if (rlo < NN) {
                    float o0 = mish2(acc[mi][ni][0] + b0);
                    float o1 = mish2(acc[mi][ni][1] + b1);
                    if (write_f32) *(float2*)&hout[rlo * 128 + col] = make_float2(o0, o1);
                    uint32_t hh, ll;
                    split2(o0, o1, hh, ll);
                    *(uint32_t*)&outH[rlo * 128 + col] = hh;
                    *(uint32_t*)&outL[rlo * 128 + col] = ll;
                }
                if (rhi < NN) {
                    float o0 = mish2(acc[mi][ni][2] + b0);
                    float o1 = mish2(acc[mi][ni][3] + b1);
                    if (write_f32) *(float2*)&hout[rhi * 128 + col] = make_float2(o0, o1);
                    uint32_t hh, ll;
                    split2(o0, o1, hh, ll);
                    *(uint32_t*)&outH[rhi * 128 + col] = hh;
                    *(uint32_t*)&outL[rhi * 128 + col] = ll;
                }
            }
        }
    }
}

// ================= persistent pipelined head (256 threads): out = h @ Wh^T + b =========
#define H_SM_A    512
#define H_SM_W    (512 + 4 * 18432)
#define H_SMEM_BYTES (H_SM_W + 36864)

__global__ __launch_bounds__(256, 1) void k_head_tc(
    const uint16_t* __restrict__ xH, const uint16_t* __restrict__ xL,
    const uint16_t* __restrict__ wprep, const float* __restrict__ bias,
    float* __restrict__ outp) {
    extern __shared__ __align__(16) char smem[];
    int t = threadIdx.x;
    int wid = t >> 5, lane = t & 31;
    int g = lane >> 2, q = lane & 3;

    {
        const uint4* src = (const uint4*)wprep;
        uint4* dst = (uint4*)(smem + H_SM_W);
        #pragma unroll
        for (int it = 0; it < 9; it++) dst[t + it * 256] = src[t + it * 256];
    }
    if (t < 64) ((float*)smem)[t] = bias[t];

    uint32_t smemS = (uint32_t)__cvta_generic_to_shared(smem);
    int tile4 = lane >> 3, r8 = lane & 7;
    uint32_t laneA = (uint32_t)((((tile4 & 1) * 8 + r8) * 144) + (tile4 >> 1) * 16);
    uint32_t laneB = (uint32_t)((((tile4 >> 1) * 8 + r8) * 144) + (tile4 & 1) * 16);
    uint32_t aRow0 = (uint32_t)((wid * 16) * 144);

    StageRegsT<4> sr;
    stage_load_planes<4>(sr, xH, xL, blockIdx.x * 128, 0, t, 256);
    stage_store<4>(sr, smem + H_SM_A, smem + H_SM_A + 18432, t, 256);
    __syncthreads();

    for (int tile = blockIdx.x; tile < NTILES; tile += GRID_P) {
        int row0 = tile * 128;

        float acc[8][4];
        #pragma unroll
        for (int ni = 0; ni < 8; ni++)
            #pragma unroll
            for (int r = 0; r < 4; r++) acc[ni][r] = 0.f;

        #pragma unroll
        for (int c = 0; c < 2; c++) {
            if (c < 1) stage_load_planes<4>(sr, xH, xL, row0, 64, t, 256);
            else       stage_load_planes<4>(sr, xH, xL, row0 + GRID_P * 128, 0, t, 256);

            uint32_t AhS = smemS + H_SM_A + (c & 1) * 36864 + aRow0 + laneA;
            uint32_t AlS = AhS + 18432;
            uint32_t BhS = smemS + H_SM_W + c * 9216 + laneB;
            uint32_t BlS = BhS + 2 * 9216;

            #pragma unroll
            for (int ks = 0; ks < 4; ks++) {
                uint32_t ksb = ks * 32;
                uint32_t ah[4], al[4];
                ldsm4(ah, AhS + ksb);
                ldsm4(al, AlS + ksb);
                #pragma unroll
                for (int nip = 0; nip < 4; nip++) {
                    uint32_t bh[4], bl[4];
                    ldsm4(bh, BhS + nip * (16 * 144) + ksb);
                    ldsm4(bl, BlS + nip * (16 * 144) + ksb);
                    mma_bf16(acc[2 * nip],     ah, bh);
                    mma_bf16(acc[2 * nip],     al, bh);
                    mma_bf16(acc[2 * nip],     ah, bl);
                    mma_bf16(acc[2 * nip + 1], ah, bh + 2);
                    mma_bf16(acc[2 * nip + 1], al, bh + 2);
                    mma_bf16(acc[2 * nip + 1], ah, bl + 2);
                }
            }

            {
                char* AHn = smem + H_SM_A + ((c + 1) & 1) * 36864;
                stage_store<4>(sr, AHn, AHn + 18432, t, 256);
                __syncthreads();
            }
        }

        const float* bsm = (const float*)smem;
        #pragma unroll
        for (int ni = 0; ni < 8; ni++) {
            int col = ni * 8 + 2 * q;
            float b0 = bsm[col], b1 = bsm[col + 1];
            int rlo = row0 + wid * 16 + g;
            int rhi = rlo + 8;
            if (rlo < NN)
                *(float2*)&outp[rlo * 64 + col] =
                    make_float2(acc[ni][0] + b0, acc[ni][1] + b1);
            if (rhi < NN)
                *(float2*)&outp[rhi * 64 + col] =
                    make_float2(acc[ni][2] + b0, acc[ni][3] + b1);
        }
    }

    // tail: re-zero counters for the next graph replay (this kernel is last)
    int gtid = blockIdx.x * 256 + t;
    for (int i = gtid; i < NN; i += GRID_P * 256) { g_cnt[i] = 0; g_cur[i] = 0; }
    if (gtid < NB_SCAN) g_pkt[gtid] = 0ull;
}

// ---------------- launch ----------------
extern "C" void kernel_launch(void* const* d_in, const int* in_sizes, int n_in,
                              void* d_out, int out_size) {
    (void)in_sizes; (void)n_in; (void)out_size;
    const float* x      = (const float*)d_in[0];
    const int*   edge   = (const int*)d_in[1];     // int32 on device (JAX x64 off)
    const float* W_l0   = (const float*)d_in[2];
    const float* b_l0   = (const float*)d_in[3];
    const float* W_r0   = (const float*)d_in[4];
    const float* W_l1   = (const float*)d_in[5];
    const float* b_l1   = (const float*)d_in[6];
    const float* W_r1   = (const float*)d_in[7];
    const float* W_head = (const float*)d_in[8];
    const float* b_head = (const float*)d_in[9];
    float* out = (float*)d_out;

    cudaFuncSetAttribute(k_layer_tc, cudaFuncAttributeMaxDynamicSharedMemorySize,
                         L_SMEM_BYTES);
    cudaFuncSetAttribute(k_head_tc, cudaFuncAttributeMaxDynamicSharedMemorySize,
                         H_SMEM_BYTES);

    float *h_p;
    uint16_t *aggH_p, *aggL_p, *xH_p, *xL_p, *wb0_p, *wb1_p, *wbh_p;
    cudaGetSymbolAddress((void**)&h_p,    g_h);
    cudaGetSymbolAddress((void**)&aggH_p, g_aggH);
    cudaGetSymbolAddress((void**)&aggL_p, g_aggL);
    cudaGetSymbolAddress((void**)&xH_p,   g_xH);
    cudaGetSymbolAddress((void**)&xL_p,   g_xL);
    cudaGetSymbolAddress((void**)&wb0_p,  g_WB0);
    cudaGetSymbolAddress((void**)&wb1_p,  g_WB1);
    cudaGetSymbolAddress((void**)&wbh_p,  g_WBh);

    int agg_grid = (NN * 2 * 32 + 255) / 256;   // two warps per node

    // counters zero at load; re-zeroed by k_head_tc tail each call.
    // launch index 3 (the ncu-profiled slot) is k_aggregate.
    k_hist_prep<<<HIST_BLOCKS + 72, 256>>>(edge, W_l0, W_r0, W_l1, W_r1, W_head); // 0
    k_scan<<<NB_SCAN, 512>>>();                                                   // 1
    k_scatter<<<EE / 256, 256>>>(edge);                                           // 2
    k_aggregate<<<agg_grid, 256>>>(x, aggH_p, aggL_p);                            // 3 <- profiled
    k_layer_tc<<<GRID_P, 512, L_SMEM_BYTES>>>(aggH_p, aggL_p, nullptr, nullptr, x,
                                              wb0_p, b_l0, h_p, xH_p, xL_p, 1);   // 4
    k_aggregate<<<agg_grid, 256>>>(h_p, aggH_p, aggL_p);                          // 5
    k_layer_tc<<<GRID_P, 512, L_SMEM_BYTES>>>(aggH_p, aggL_p, xH_p, xL_p, nullptr,
                                              wb1_p, b_l1, h_p, xH_p, xL_p, 0);   // 6
    k_head_tc<<<GRID_P, 256, H_SMEM_BYTES>>>(xH_p, xL_p, wbh_p, b_head, out);     // 7
}

// round 17
// speedup vs baseline: 1.3078x; 1.0781x over previous
#include <cuda_runtime.h>
#include <cuda_bf16.h>
#include <cstdint>

#define NN 100000
#define EE 1600000
#define DH 128
#define NTILES ((NN + 127) / 128)   // 782
#define GRID_P 148
#define NB_SCAN ((NN + 511) / 512)  // 196
#define HIST4_BLOCKS ((EE + 1023) / 1024)   // 1563
#define SCAT4_BLOCKS ((EE + 1023) / 1024)   // 1563

// ---------------- device scratch ----------------
__device__ __align__(16) uint16_t g_aggH[NN * DH];
__device__ __align__(16) uint16_t g_aggL[NN * DH];
__device__ __align__(16) uint16_t g_xH[NN * DH];
__device__ __align__(16) uint16_t g_xL[NN * DH];
__device__ float g_h[NN * DH];
__device__ int   g_cnt[NN];          // zero-init at load; re-zeroed by k_head_tc tail
__device__ int   g_cur[NN];
__device__ int   g_off[NN];
__device__ int   g_srcsorted[EE];
__device__ unsigned long long g_pkt[NB_SCAN];
__device__ __align__(16) uint16_t g_WB0[2 * 4 * 128 * 72];
__device__ __align__(16) uint16_t g_WB1[2 * 4 * 128 * 72];
__device__ __align__(16) uint16_t g_WBh[2 * 2 * 64 * 72];

// ---------------- helpers ----------------
__device__ __forceinline__ void split2(float a, float b, uint32_t& h, uint32_t& l) {
    __nv_bfloat16 ha = __float2bfloat16_rn(a);
    __nv_bfloat16 hb = __float2bfloat16_rn(b);
    __nv_bfloat16 la = __float2bfloat16_rn(a - __bfloat162float(ha));
    __nv_bfloat16 lb = __float2bfloat16_rn(b - __bfloat162float(hb));
    h = (uint32_t)__bfloat16_as_ushort(ha) | ((uint32_t)__bfloat16_as_ushort(hb) << 16);
    l = (uint32_t)__bfloat16_as_ushort(la) | ((uint32_t)__bfloat16_as_ushort(lb) << 16);
}
__device__ __forceinline__ float mish2(float v) {
    float t = __expf(fminf(v, 30.f));
    float r = t * t + 2.f * t;
    return v * (r / (r + 2.f));
}
__device__ __forceinline__ void mma_bf16(float* c, const uint32_t* a, const uint32_t* b) {
    asm volatile(
        "mma.sync.aligned.m16n8k16.row.col.f32.bf16.bf16.f32 "
        "{%0,%1,%2,%3}, {%4,%5,%6,%7}, {%8,%9}, {%0,%1,%2,%3};"
        : "+f"(c[0]), "+f"(c[1]), "+f"(c[2]), "+f"(c[3])
        : "r"(a[0]), "r"(a[1]), "r"(a[2]), "r"(a[3]), "r"(b[0]), "r"(b[1]));
}
__device__ __forceinline__ void ldsm4(uint32_t* r, uint32_t a) {
    asm volatile("ldmatrix.sync.aligned.m8n8.x4.shared.b16 {%0,%1,%2,%3}, [%4];"
        : "=r"(r[0]), "=r"(r[1]), "=r"(r[2]), "=r"(r[3]) : "r"(a));
}

// ---------------- fused hist (4 edges/thread) + weight prep ----------------
__device__ __forceinline__ void prep_layer_elem(const float* Wl, const float* Wr,
                                                uint16_t* outw, int idx) {
    int n = idx >> 6;
    int kg = (idx & 63) * 4;
    const float* Ws = (kg < 128) ? Wl : Wr;
    float4 v = *(const float4*)&Ws[n * 128 + (kg & 127)];
    uint32_t h01, h23, l01, l23;
    split2(v.x, v.y, h01, l01);
    split2(v.z, v.w, h23, l23);
    int c = kg >> 6, kk = kg & 63;
    *(uint2*)&outw[((0 * 4 + c) * 128 + n) * 72 + kk] = make_uint2(h01, h23);
    *(uint2*)&outw[((4 + c) * 128 + n) * 72 + kk]     = make_uint2(l01, l23);
}
__global__ void k_hist_prep(const int* __restrict__ edge,
                            const float* __restrict__ Wl0, const float* __restrict__ Wr0,
                            const float* __restrict__ Wl1, const float* __restrict__ Wr1,
                            const float* __restrict__ Wh) {
    int b = blockIdx.x;
    int t = threadIdx.x;
    if (b < HIST4_BLOCKS) {
        int e0 = b * 1024 + t;
        int d[4];
        #pragma unroll
        for (int i = 0; i < 4; i++) {
            int e = e0 + i * 256;
            d[i] = (e < EE) ? edge[EE + e] : -1;
        }
        #pragma unroll
        for (int i = 0; i < 4; i++)
            if (d[i] >= 0) atomicAdd(&g_cnt[d[i]], 1);
    } else {
        int pb = b - HIST4_BLOCKS;   // 0..71
        if (pb < 32) {
            prep_layer_elem(Wl0, Wr0, g_WB0, pb * 256 + t);
        } else if (pb < 64) {
            prep_layer_elem(Wl1, Wr1, g_WB1, (pb - 32) * 256 + t);
        } else {
            int idx = (pb - 64) * 256 + t;
            int n = idx >> 5;
            int kg = (idx & 31) * 4;
            float4 v = *(const float4*)&Wh[n * 128 + kg];
            uint32_t h01, h23, l01, l23;
            split2(v.x, v.y, h01, l01);
            split2(v.z, v.w, h23, l23);
            int c = kg >> 6, kk = kg & 63;
            *(uint2*)&g_WBh[((0 * 2 + c) * 64 + n) * 72 + kk] = make_uint2(h01, h23);
            *(uint2*)&g_WBh[((2 + c) * 64 + n) * 72 + kk]     = make_uint2(l01, l23);
        }
    }
}
// single-pass decoupled-lookback exclusive scan of g_cnt -> g_off
__global__ void k_scan() {
    __shared__ int s[512];
    __shared__ int s_prefix;
    int t = threadIdx.x, b = blockIdx.x;
    int i = b * 512 + t;
    int v = (i < NN) ? g_cnt[i] : 0;
    s[t] = v;
    __syncthreads();
    #pragma unroll
    for (int off = 1; off < 512; off <<= 1) {
        int add = (t >= off) ? s[t - off] : 0;
        __syncthreads();
        s[t] += add;
        __syncthreads();
    }
    int total = s[511];
    if (t == 0) {
        atomicExch(&g_pkt[b], (1ull << 62) | (unsigned long long)total);
        long long prefix = 0;
        for (int j = b - 1; j >= 0; j--) {
            unsigned long long p;
            do { p = atomicAdd(&g_pkt[j], 0ull); } while ((p >> 62) == 0ull);
            prefix += (long long)(p & 0x3FFFFFFFFFFFFFFFull);
            if ((p >> 62) == 2ull) break;
        }
        atomicExch(&g_pkt[b], (2ull << 62) | (unsigned long long)(prefix + total));
        s_prefix = (int)prefix;
    }
    __syncthreads();
    if (i < NN) g_off[i] = s[t] - v + s_prefix;
}
// scatter: 4 edges/thread for atomic MLP
__global__ void k_scatter(const int* __restrict__ edge) {
    int e0 = blockIdx.x * 1024 + threadIdx.x;
    int s[4], d[4], p[4];
    #pragma unroll
    for (int i = 0; i < 4; i++) {
        int e = e0 + i * 256;
        if (e < EE) { s[i] = edge[e]; d[i] = edge[EE + e]; }
        else        { s[i] = -1; d[i] = 0; }
    }
    #pragma unroll
    for (int i = 0; i < 4; i++)
        p[i] = (s[i] >= 0) ? atomicAdd(&g_cur[d[i]], 1) : 0;
    #pragma unroll
    for (int i = 0; i < 4; i++)
        if (s[i] >= 0) g_srcsorted[g_off[d[i]] + p[i]] = s[i];
}

// ---------------- aggregation: R14 shape (one warp/node, float4, MLP-4, dual acc) ----
__global__ __launch_bounds__(256) void k_aggregate(const float* __restrict__ feat,
                                                   uint16_t* __restrict__ outH,
                                                   uint16_t* __restrict__ outL) {
    int w = (blockIdx.x * blockDim.x + threadIdx.x) >> 5;
    if (w >= NN) return;
    int lane = threadIdx.x & 31;
    int start = g_off[w];
    int c = g_cnt[w];
    const float4* f4 = (const float4*)feat;
    float4 acc0 = make_float4(0.f, 0.f, 0.f, 0.f);
    float4 acc1 = make_float4(0.f, 0.f, 0.f, 0.f);
    for (int base = 0; base < c; base += 32) {
        int idx = (base + lane < c) ? g_srcsorted[start + base + lane] : 0;
        int m = min(32, c - base);
        int j = 0;
        for (; j + 4 <= m; j += 4) {
            int s0 = __shfl_sync(0xffffffffu, idx, j + 0);
            int s1 = __shfl_sync(0xffffffffu, idx, j + 1);
            int s2 = __shfl_sync(0xffffffffu, idx, j + 2);
            int s3 = __shfl_sync(0xffffffffu, idx, j + 3);
            float4 v0 = __ldg(&f4[s0 * 32 + lane]);
            float4 v1 = __ldg(&f4[s1 * 32 + lane]);
            float4 v2 = __ldg(&f4[s2 * 32 + lane]);
            float4 v3 = __ldg(&f4[s3 * 32 + lane]);
            acc0.x += v0.x; acc0.y += v0.y; acc0.z += v0.z; acc0.w += v0.w;
            acc1.x += v1.x; acc1.y += v1.y; acc1.z += v1.z; acc1.w += v1.w;
            acc0.x += v2.x; acc0.y += v2.y; acc0.z += v2.z; acc0.w += v2.w;
            acc1.x += v3.x; acc1.y += v3.y; acc1.z += v3.z; acc1.w += v3.w;
        }
        for (; j < m; j++) {
            int s = __shfl_sync(0xffffffffu, idx, j);
            float4 v = __ldg(&f4[s * 32 + lane]);
            acc0.x += v.x; acc0.y += v.y; acc0.z += v.z; acc0.w += v.w;
        }
    }
    float4 acc = make_float4(acc0.x + acc1.x, acc0.y + acc1.y,
                             acc0.z + acc1.z, acc0.w + acc1.w);
    float inv = 1.f / fmaxf((float)c, 1.f);
    acc.x *= inv; acc.y *= inv; acc.z *= inv; acc.w *= inv;
    uint32_t h01, h23, l01, l23;
    split2(acc.x, acc.y, h01, l01);
    split2(acc.z, acc.w, h23, l23);
    *(uint2*)&outH[w * 128 + lane * 4] = make_uint2(h01, h23);
    *(uint2*)&outL[w * 128 + lane * 4] = make_uint2(l01, l23);
}

// ---------------- staging primitives (templated on per-thread iter count) ----------------
template <int NIT> struct StageRegsT { uint4 rH[NIT], rL[NIT]; };

template <int NIT>
__device__ __forceinline__ void stage_load_planes(StageRegsT<NIT>& s, const uint16_t* pH,
                                                  const uint16_t* pL, int row0, int cb,
                                                  int t, int stride) {
    #pragma unroll
    for (int i = 0; i < NIT; i++) {
        int v = t + i * stride, row = v >> 3, f = v & 7, gr = row0 + row;
        if (gr < NN) {
            s.rH[i] = *(const uint4*)(pH + gr * 128 + cb + f * 8);
            s.rL[i] = *(const uint4*)(pL + gr * 128 + cb + f * 8);
        } else {
            s.rH[i] = make_uint4(0, 0, 0, 0);
            s.rL[i] = make_uint4(0, 0, 0, 0);
        }
    }
}
template <int NIT>
__device__ __forceinline__ void stage_load_f32(StageRegsT<NIT>& s, const float* xf,
                                               int row0, int cb16, int t, int stride) {
    const float4* x4 = (const float4*)xf;
    #pragma unroll
    for (int i = 0; i < NIT; i++) {
        int v = t + i * stride, row = v >> 3, f = v & 7, gr = row0 + row;
        float4 a = make_float4(0.f, 0.f, 0.f, 0.f);
        float4 b = make_float4(0.f, 0.f, 0.f, 0.f);
        if (gr < NN) {
            a = x4[gr * 32 + cb16 + f * 2];
            b = x4[gr * 32 + cb16 + f * 2 + 1];
        }
        uint32_t h01, h23, h45, h67, l01, l23, l45, l67;
        split2(a.x, a.y, h01, l01);
        split2(a.z, a.w, h23, l23);
        split2(b.x, b.y, h45, l45);
        split2(b.z, b.w, h67, l67);
        s.rH[i] = make_uint4(h01, h23, h45, h67);
        s.rL[i] = make_uint4(l01, l23, l45, l67);
    }
}
template <int NIT>
__device__ __forceinline__ void stage_store(const StageRegsT<NIT>& s, char* AH, char* AL,
                                            int t, int stride) {
    #pragma unroll
    for (int i = 0; i < NIT; i++) {
        int v = t + i * stride, row = v >> 3, f = v & 7;
        *(uint4*)(AH + row * 144 + f * 16) = s.rH[i];
        *(uint4*)(AL + row * 144 + f * 16) = s.rL[i];
    }
}

// ================= persistent pipelined layer GEMM: 512 threads, 16 warps =========
// warp tile 32x32; smem: bias 512 | A dbuf 2x36864 | W 147456 => 221696 B
#define L_SM_A    512
#define L_SM_W    (512 + 4 * 18432)
#define L_SMEM_BYTES (L_SM_W + 147456)

__global__ __launch_bounds__(512, 1) void k_layer_tc(
    const uint16_t* __restrict__ aggH, const uint16_t* __restrict__ aggL,
    const uint16_t* xH, const uint16_t* xL,
    const float* __restrict__ xf32,
    const uint16_t* __restrict__ wprep, const float* __restrict__ bias,
    float* __restrict__ hout, uint16_t* outH, uint16_t* outL, int write_f32) {
    extern __shared__ __align__(16) char smem[];
    int t = threadIdx.x;
    int wid = t >> 5, lane = t & 31;
    int g = lane >> 2, q = lane & 3;
    int wm = wid & 3, wn = wid >> 2;    // rows wm*32.., cols wn*32..

    {
        const uint4* src = (const uint4*)wprep;
        uint4* dst = (uint4*)(smem + L_SM_W);
        #pragma unroll
        for (int it = 0; it < 18; it++) dst[t + it * 512] = src[t + it * 512];
    }
    if (t < 128) ((float*)smem)[t] = bias[t];

    uint32_t smemS = (uint32_t)__cvta_generic_to_shared(smem);
    int tile4 = lane >> 3, r8 = lane & 7;
    uint32_t laneA = (uint32_t)((((tile4 & 1) * 8 + r8) * 144) + (tile4 >> 1) * 16);
    uint32_t laneB = (uint32_t)((((tile4 >> 1) * 8 + r8) * 144) + (tile4 & 1) * 16);
    uint32_t aRow0 = (uint32_t)((wm * 32) * 144);
    uint32_t bRow0 = (uint32_t)((wn * 32) * 144);

    auto load_chunk = [&](StageRegsT<2>& s, int cc, int r0) {
        if (cc < 2)
            stage_load_planes<2>(s, aggH, aggL, r0, cc * 64, t, 512);
        else if (xf32)
            stage_load_f32<2>(s, xf32, r0, (cc - 2) * 16, t, 512);
        else
            stage_load_planes<2>(s, xH, xL, r0, (cc - 2) * 64, t, 512);
    };

    StageRegsT<2> sr;
    load_chunk(sr, 0, blockIdx.x * 128);
    stage_store<2>(sr, smem + L_SM_A, smem + L_SM_A + 18432, t, 512);
    __syncthreads();

    for (int tile = blockIdx.x; tile < NTILES; tile += GRID_P) {
        int row0 = tile * 128;

        float acc[2][4][4];
        #pragma unroll
        for (int mi = 0; mi < 2; mi++)
            #pragma unroll
            for (int ni = 0; ni < 4; ni++)
                #pragma unroll
                for (int r = 0; r < 4; r++) acc[mi][ni][r] = 0.f;

        #pragma unroll
        for (int c = 0; c < 4; c++) {
            if (c < 3) load_chunk(sr, c + 1, row0);
            else       load_chunk(sr, 0, row0 + GRID_P * 128);

            uint32_t AhS = smemS + L_SM_A + (c & 1) * 36864 + aRow0 + laneA;
            uint32_t AlS = AhS + 18432;
            uint32_t BhS = smemS + L_SM_W + c * 18432 + bRow0 + laneB;
            uint32_t BlS = BhS + 4 * 18432;

            #pragma unroll
            for (int ks = 0; ks < 4; ks++) {
                uint32_t ksb = ks * 32;
                uint32_t ah[2][4], al[2][4];
                ldsm4(ah[0], AhS + ksb);
                ldsm4(ah[1], AhS + 16 * 144 + ksb);
                ldsm4(al[0], AlS + ksb);
                ldsm4(al[1], AlS + 16 * 144 + ksb);
                #pragma unroll
                for (int nj = 0; nj < 2; nj++) {
                    uint32_t bh[4], bl[4];
                    ldsm4(bh, BhS + nj * (16 * 144) + ksb);
                    ldsm4(bl, BlS + nj * (16 * 144) + ksb);
                    #pragma unroll
                    for (int mi = 0; mi < 2; mi++) {
                        mma_bf16(acc[mi][2 * nj],     ah[mi], bh);
                        mma_bf16(acc[mi][2 * nj],     al[mi], bh);
                        mma_bf16(acc[mi][2 * nj],     ah[mi], bl);
                        mma_bf16(acc[mi][2 * nj + 1], ah[mi], bh + 2);
                        mma_bf16(acc[mi][2 * nj + 1], al[mi], bh + 2);
                        mma_bf16(acc[mi][2 * nj + 1], ah[mi], bl + 2);
                    }
                }
            }

            {
                char* AHn = smem + L_SM_A + ((c + 1) & 1) * 36864;
                stage_store<2>(sr, AHn, AHn + 18432, t, 512);
                __syncthreads();
            }
        }

        const float* bsm = (const float*)smem;
        #pragma unroll
        for (int mi = 0; mi < 2; mi++) {
            #pragma unroll
            for (int ni = 0; ni < 4; ni++) {
                int col = wn * 32 + ni * 8 + 2 * q;
                float b0 = bsm[col], b1 = bsm[col + 1];
                int rlo = row0 + wm * 32 + mi * 16 + g;
                int rhi = rlo + 8;
                if (rlo < NN) {
                    float o0 = mish2(acc[mi][ni][0] + b0);
                    float o1 = mish2(acc[mi][ni][1] + b1);
                    if (write_f32) *(float2*)&hout[rlo * 128 + col] = make_float2(o0, o1);
                    uint32_t hh, ll;
                    split2(o0, o1, hh, ll);
                    *(uint32_t*)&outH[rlo * 128 + col] = hh;
                    *(uint32_t*)&outL[rlo * 128 + col] = ll;
                }
                if (rhi < NN) {
                    float o0 = mish2(acc[mi][ni][2] + b0);
                    float o1 = mish2(acc[mi][ni][3] + b1);
                    if (write_f32) *(float2*)&hout[rhi * 128 + col] = make_float2(o0, o1);
                    uint32_t hh, ll;
                    split2(o0, o1, hh, ll);
                    *(uint32_t*)&outH[rhi * 128 + col] = hh;
                    *(uint32_t*)&outL[rhi * 128 + col] = ll;
                }
            }
        }
    }
}

// ================= persistent pipelined head (256 threads): out = h @ Wh^T + b =========
#define H_SM_A    512
#define H_SM_W    (512 + 4 * 18432)
#define H_SMEM_BYTES (H_SM_W + 36864)

__global__ __launch_bounds__(256, 1) void k_head_tc(
    const uint16_t* __restrict__ xH, const uint16_t* __restrict__ xL,
    const uint16_t* __restrict__ wprep, const float* __restrict__ bias,
    float* __restrict__ outp) {
    extern __shared__ __align__(16) char smem[];
    int t = threadIdx.x;
    int wid = t >> 5, lane = t & 31;
    int g = lane >> 2, q = lane & 3;

    {
        const uint4* src = (const uint4*)wprep;
        uint4* dst = (uint4*)(smem + H_SM_W);
        #pragma unroll
        for (int it = 0; it < 9; it++) dst[t + it * 256] = src[t + it * 256];
    }
    if (t < 64) ((float*)smem)[t] = bias[t];

    uint32_t smemS = (uint32_t)__cvta_generic_to_shared(smem);
    int tile4 = lane >> 3, r8 = lane & 7;
    uint32_t laneA = (uint32_t)((((tile4 & 1) * 8 + r8) * 144) + (tile4 >> 1) * 16);
    uint32_t laneB = (uint32_t)((((tile4 >> 1) * 8 + r8) * 144) + (tile4 & 1) * 16);
    uint32_t aRow0 = (uint32_t)((wid * 16) * 144);

    StageRegsT<4> sr;
    stage_load_planes<4>(sr, xH, xL, blockIdx.x * 128, 0, t, 256);
    stage_store<4>(sr, smem + H_SM_A, smem + H_SM_A + 18432, t, 256);
    __syncthreads();

    for (int tile = blockIdx.x; tile < NTILES; tile += GRID_P) {
        int row0 = tile * 128;

        float acc[8][4];
        #pragma unroll
        for (int ni = 0; ni < 8; ni++)
            #pragma unroll
            for (int r = 0; r < 4; r++) acc[ni][r] = 0.f;

        #pragma unroll
        for (int c = 0; c < 2; c++) {
            if (c < 1) stage_load_planes<4>(sr, xH, xL, row0, 64, t, 256);
            else       stage_load_planes<4>(sr, xH, xL, row0 + GRID_P * 128, 0, t, 256);

            uint32_t AhS = smemS + H_SM_A + (c & 1) * 36864 + aRow0 + laneA;
            uint32_t AlS = AhS + 18432;
            uint32_t BhS = smemS + H_SM_W + c * 9216 + laneB;
            uint32_t BlS = BhS + 2 * 9216;

            #pragma unroll
            for (int ks = 0; ks < 4; ks++) {
                uint32_t ksb = ks * 32;
                uint32_t ah[4], al[4];
                ldsm4(ah, AhS + ksb);
                ldsm4(al, AlS + ksb);
                #pragma unroll
                for (int nip = 0; nip < 4; nip++) {
                    uint32_t bh[4], bl[4];
                    ldsm4(bh, BhS + nip * (16 * 144) + ksb);
                    ldsm4(bl, BlS + nip * (16 * 144) + ksb);
                    mma_bf16(acc[2 * nip],     ah, bh);
                    mma_bf16(acc[2 * nip],     al, bh);
                    mma_bf16(acc[2 * nip],     ah, bl);
                    mma_bf16(acc[2 * nip + 1], ah, bh + 2);
                    mma_bf16(acc[2 * nip + 1], al, bh + 2);
                    mma_bf16(acc[2 * nip + 1], ah, bl + 2);
                }
            }

            {
                char* AHn = smem + H_SM_A + ((c + 1) & 1) * 36864;
                stage_store<4>(sr, AHn, AHn + 18432, t, 256);
                __syncthreads();
            }
        }

        const float* bsm = (const float*)smem;
        #pragma unroll
        for (int ni = 0; ni < 8; ni++) {
            int col = ni * 8 + 2 * q;
            float b0 = bsm[col], b1 = bsm[col + 1];
            int rlo = row0 + wid * 16 + g;
            int rhi = rlo + 8;
            if (rlo < NN)
                *(float2*)&outp[rlo * 64 + col] =
                    make_float2(acc[ni][0] + b0, acc[ni][1] + b1);
            if (rhi < NN)
                *(float2*)&outp[rhi * 64 + col] =
                    make_float2(acc[ni][2] + b0, acc[ni][3] + b1);
        }
    }

    // tail: re-zero counters for the next graph replay (this kernel is last)
    int gtid = blockIdx.x * 256 + t;
    for (int i = gtid; i < NN; i += GRID_P * 256) { g_cnt[i] = 0; g_cur[i] = 0; }
    if (gtid < NB_SCAN) g_pkt[gtid] = 0ull;
}

// ---------------- launch ----------------
extern "C" void kernel_launch(void* const* d_in, const int* in_sizes, int n_in,
                              void* d_out, int out_size) {
    (void)in_sizes; (void)n_in; (void)out_size;
    const float* x      = (const float*)d_in[0];
    const int*   edge   = (const int*)d_in[1];     // int32 on device (JAX x64 off)
    const float* W_l0   = (const float*)d_in[2];
    const float* b_l0   = (const float*)d_in[3];
    const float* W_r0   = (const float*)d_in[4];
    const float* W_l1   = (const float*)d_in[5];
    const float* b_l1   = (const float*)d_in[6];
    const float* W_r1   = (const float*)d_in[7];
    const float* W_head = (const float*)d_in[8];
    const float* b_head = (const float*)d_in[9];
    float* out = (float*)d_out;

    cudaFuncSetAttribute(k_layer_tc, cudaFuncAttributeMaxDynamicSharedMemorySize,
                         L_SMEM_BYTES);
    cudaFuncSetAttribute(k_head_tc, cudaFuncAttributeMaxDynamicSharedMemorySize,
                         H_SMEM_BYTES);

    float *h_p;
    uint16_t *aggH_p, *aggL_p, *xH_p, *xL_p, *wb0_p, *wb1_p, *wbh_p;
    cudaGetSymbolAddress((void**)&h_p,    g_h);
    cudaGetSymbolAddress((void**)&aggH_p, g_aggH);
    cudaGetSymbolAddress((void**)&aggL_p, g_aggL);
    cudaGetSymbolAddress((void**)&xH_p,   g_xH);
    cudaGetSymbolAddress((void**)&xL_p,   g_xL);
    cudaGetSymbolAddress((void**)&wb0_p,  g_WB0);
    cudaGetSymbolAddress((void**)&wb1_p,  g_WB1);
    cudaGetSymbolAddress((void**)&wbh_p,  g_WBh);

    int agg_grid = (NN * 32 + 255) / 256;   // one warp per node (R14 shape)

    // counters zero at load; re-zeroed by k_head_tc tail each call.
    // launch index 3 (the ncu-profiled slot) is k_aggregate.
    k_hist_prep<<<HIST4_BLOCKS + 72, 256>>>(edge, W_l0, W_r0, W_l1, W_r1, W_head); // 0
    k_scan<<<NB_SCAN, 512>>>();                                                    // 1
    k_scatter<<<SCAT4_BLOCKS, 256>>>(edge);                                        // 2
    k_aggregate<<<agg_grid, 256>>>(x, aggH_p, aggL_p);                             // 3 <- profiled
    k_layer_tc<<<GRID_P, 512, L_SMEM_BYTES>>>(aggH_p, aggL_p, nullptr, nullptr, x,
                                              wb0_p, b_l0, h_p, xH_p, xL_p, 1);    // 4
    k_aggregate<<<agg_grid, 256>>>(h_p, aggH_p, aggL_p);                           // 5
    k_layer_tc<<<GRID_P, 512, L_SMEM_BYTES>>>(aggH_p, aggL_p, xH_p, xL_p, nullptr,
                                              wb1_p, b_l1, h_p, xH_p, xL_p, 0);    // 6
    k_head_tc<<<GRID_P, 256, H_SMEM_BYTES>>>(xH_p, xL_p, wbh_p, b_head, out);      // 7
}